// round 3
// baseline (speedup 1.0000x reference)
#include <cuda_runtime.h>

#define NN 4
#define CC 64
#define VV 25
#define TT 300
#define MM 2
#define HH 8
#define HD 32
#define EE 256
#define ROWS 60000   /* NN*MM*VV*TT */
#define BVH 1600     /* (NN*MM*VV) * HH = 200*8 */

#define AT_THREADS 512
#define AT_WARPS 16

// ---------------- device scratch (no allocations allowed) ----------------
__device__ float g_xt[(size_t)ROWS * CC];     // rows x 64
__device__ float g_q [(size_t)ROWS * EE];     // rows x 256
__device__ float g_k [(size_t)ROWS * EE];     // pre-scaled by 1/16
__device__ float g_v [(size_t)ROWS * EE];
__device__ float g_attn[(size_t)ROWS * EE];

// ---------------------------------------------------------------------------
// Kernel A: transpose x (N,C,V,T,M) -> g_xt[row][c], row = ((n*2+m)*V+v)*T+t
// x linear index: ((n*C+c)*V+v)*600 + tm, tm = t*2+m
// ---------------------------------------------------------------------------
__global__ __launch_bounds__(256) void kernA(const float* __restrict__ x) {
    __shared__ float sm[64][33];
    int tm0 = blockIdx.x * 32;
    int v   = blockIdx.y;
    int n   = blockIdx.z;
    int tid  = threadIdx.x;
    int lane = tid & 31;
    int crow = tid >> 5;
#pragma unroll
    for (int kk = 0; kk < 8; kk++) {
        int c  = crow + (kk << 3);
        int tm = tm0 + lane;
        float val = 0.f;
        if (tm < 600) val = x[((size_t)(n * CC + c) * VV + v) * 600 + tm];
        sm[c][lane] = val;
    }
    __syncthreads();
    int c2 = tid & 63;
    int jb = tid >> 6;
#pragma unroll
    for (int kk = 0; kk < 8; kk++) {
        int j  = jb + (kk << 2);
        int tm = tm0 + j;
        if (tm < 600) {
            int t = tm >> 1, m = tm & 1;
            size_t row = ((size_t)((n * 2 + m) * VV + v)) * TT + t;
            g_xt[row * CC + c2] = sm[c2][j];
        }
    }
}

// ---------------------------------------------------------------------------
// Kernel B: qkv = xt @ w_qkv + b_qkv   (60000 x 64 x 768)
// col < 256 -> g_q ; 256..511 -> g_k * (1/16) ; 512.. -> g_v
// Block: 64 rows x 64 cols, 256 threads, 4x4 micro-tiles.
// ---------------------------------------------------------------------------
__global__ __launch_bounds__(256) void kernB(const float* __restrict__ w,
                                             const float* __restrict__ b) {
    __shared__ float sx[64 * 68];   // sx[e*68 + r]  (x tile transposed)
    __shared__ float sw[64 * 68];   // sw[e*68 + cc]
    int tid = threadIdx.x;
    int c0 = blockIdx.x * 64;
    int r0 = blockIdx.y * 64;
#pragma unroll
    for (int p = 0; p < 16; p++) {
        int idx = tid + p * 256;
        int a = idx >> 6;       // r for x-tile, e for w-tile
        int e = idx & 63;       // e for x-tile, cc for w-tile
        int row = r0 + a;
        float vx = 0.f;
        if (row < ROWS) vx = g_xt[(size_t)row * CC + e];
        sx[e * 68 + a] = vx;
        sw[a * 68 + e] = w[(size_t)a * 768 + c0 + e];
    }
    __syncthreads();
    int tx = tid & 15, ty = tid >> 4;
    float acc[4][4];
#pragma unroll
    for (int i = 0; i < 4; i++)
#pragma unroll
        for (int j = 0; j < 4; j++)
            acc[i][j] = b[c0 + tx * 4 + j];
#pragma unroll
    for (int e = 0; e < 64; e++) {
        float4 a4 = *(const float4*)&sx[e * 68 + ty * 4];
        float4 b4 = *(const float4*)&sw[e * 68 + tx * 4];
        float av[4] = {a4.x, a4.y, a4.z, a4.w};
        float bv[4] = {b4.x, b4.y, b4.z, b4.w};
#pragma unroll
        for (int i = 0; i < 4; i++)
#pragma unroll
            for (int j = 0; j < 4; j++)
                acc[i][j] = fmaf(av[i], bv[j], acc[i][j]);
    }
#pragma unroll
    for (int i = 0; i < 4; i++) {
        int row = r0 + ty * 4 + i;
        if (row < ROWS) {
#pragma unroll
            for (int j = 0; j < 4; j++) {
                int col = c0 + tx * 4 + j;
                float val = acc[i][j];
                if (col < 256)      g_q[(size_t)row * EE + col] = val;
                else if (col < 512) g_k[(size_t)row * EE + col - 256] = val * 0.0625f;
                else                g_v[(size_t)row * EE + col - 512] = val;
            }
        }
    }
}

// ---------------------------------------------------------------------------
// Kernel Attn: one block per (bv, h). smem: K, V (stride 33), bias table
// (599x32, stride 33), per-warp prob rows. Warp per query row.
// score_j = sum_d q[d] * (ks[j][d] + bias[l+299-j][d])   (k pre-scaled)
// ---------------------------------------------------------------------------
__global__ __launch_bounds__(AT_THREADS) void kernAttn(const float* __restrict__ bias_table) {
    extern __shared__ float smem[];
    float* sk = smem;                    // 300*33
    float* sv = sk + 300 * 33;           // 300*33
    float* sb = sv + 300 * 33;           // 599*33
    float* sp = sb + 599 * 33;           // AT_WARPS*304
    int head = blockIdx.x;
    int bv = head >> 3;
    int h  = head & 7;
    size_t row0 = (size_t)bv * TT;
    int tid = threadIdx.x;

    for (int idx = tid; idx < TT * HD; idx += AT_THREADS) {
        int j = idx >> 5, d = idx & 31;
        size_t g = (row0 + j) * EE + h * HD + d;
        sk[j * 33 + d] = g_k[g];
        sv[j * 33 + d] = g_v[g];
    }
    for (int idx = tid; idx < 599 * HD; idx += AT_THREADS) {
        int r = idx >> 5, d = idx & 31;
        sb[r * 33 + d] = bias_table[idx];
    }
    __syncthreads();

    int w = tid >> 5, lane = tid & 31;
    float* pw = sp + w * 304;

    for (int l = w; l < TT; l += AT_WARPS) {
        const float4* qrow4 = (const float4*)(g_q + (row0 + l) * EE + h * HD);
        float qr[32];
#pragma unroll
        for (int d4 = 0; d4 < 8; d4++) {
            float4 t4 = __ldg(qrow4 + d4);
            qr[d4 * 4 + 0] = t4.x; qr[d4 * 4 + 1] = t4.y;
            qr[d4 * 4 + 2] = t4.z; qr[d4 * 4 + 3] = t4.w;
        }
        float acc[10];
#pragma unroll
        for (int jj = 0; jj < 10; jj++) {
            int j = lane + (jj << 5);
            if (j < TT) {
                const float* kj = sk + j * 33;
                const float* bj = sb + (l + 299 - j) * 33;
                float a = 0.f;
#pragma unroll
                for (int d = 0; d < 32; d++) {
                    a = fmaf(qr[d], kj[d], a);
                    a = fmaf(qr[d], bj[d], a);
                }
                acc[jj] = a;
            } else {
                acc[jj] = -3.0e38f;
            }
        }
        // softmax over 300 j's spread across lanes
        float mx = acc[0];
#pragma unroll
        for (int jj = 1; jj < 10; jj++) mx = fmaxf(mx, acc[jj]);
#pragma unroll
        for (int off = 16; off > 0; off >>= 1)
            mx = fmaxf(mx, __shfl_xor_sync(0xffffffffu, mx, off));
        float s = 0.f;
#pragma unroll
        for (int jj = 0; jj < 10; jj++) {
            int j = lane + (jj << 5);
            float e = (j < TT) ? __expf(acc[jj] - mx) : 0.f;
            acc[jj] = e;
            s += e;
        }
#pragma unroll
        for (int off = 16; off > 0; off >>= 1)
            s += __shfl_xor_sync(0xffffffffu, s, off);
        float inv = 1.0f / s;
#pragma unroll
        for (int jj = 0; jj < 10; jj++) {
            int j = lane + (jj << 5);
            if (j < TT) pw[j] = acc[jj] * inv;
        }
        __syncwarp();
        // PV: lane = d
        float accd = 0.f;
#pragma unroll 4
        for (int j = 0; j < TT; j++)
            accd = fmaf(pw[j], sv[j * 33 + lane], accd);
        g_attn[(row0 + l) * EE + h * HD + lane] = accd;
        __syncwarp();
    }
}

// ---------------------------------------------------------------------------
// Kernel Merge: out = attn @ w_merge + b_merge, then scatter to (N,C,V,T,M)
// Block: 4 rows x 64 cols, w_merge (64KB) in dynamic smem.
// ---------------------------------------------------------------------------
__global__ __launch_bounds__(256) void kernMerge(const float* __restrict__ wm,
                                                 const float* __restrict__ bm,
                                                 float* __restrict__ out) {
    extern __shared__ float sw[];   // 256*64
    int tid = threadIdx.x;
    for (int idx = tid; idx < 256 * 64; idx += 256) sw[idx] = wm[idx];
    __syncthreads();
    int rl = tid >> 6, c = tid & 63;
    size_t row = (size_t)blockIdx.x * 4 + rl;
    const float4* arow4 = (const float4*)(g_attn + row * EE);
    float acc = bm[c];
#pragma unroll 8
    for (int e4 = 0; e4 < 64; e4++) {
        float4 a = __ldg(arow4 + e4);
        int e = e4 * 4;
        acc = fmaf(a.x, sw[e * 64 + c], acc);
        acc = fmaf(a.y, sw[(e + 1) * 64 + c], acc);
        acc = fmaf(a.z, sw[(e + 2) * 64 + c], acc);
        acc = fmaf(a.w, sw[(e + 3) * 64 + c], acc);
    }
    int t  = (int)(row % 300);
    int vv = (int)(row / 300);
    int v  = vv % 25;
    int nm = vv / 25;
    int m  = nm & 1;
    int n  = nm >> 1;
    out[(((size_t)(n * CC + c) * VV + v) * TT + t) * MM + m] = acc;
}

// ---------------------------------------------------------------------------
extern "C" void kernel_launch(void* const* d_in, const int* in_sizes, int n_in,
                              void* d_out, int out_size) {
    const float* x          = (const float*)d_in[0];
    const float* w_qkv      = (const float*)d_in[1];
    const float* b_qkv      = (const float*)d_in[2];
    const float* w_merge    = (const float*)d_in[3];
    const float* b_merge    = (const float*)d_in[4];
    const float* bias_table = (const float*)d_in[5];
    float* out = (float*)d_out;

    int smem_attn  = (300 * 33 * 2 + 599 * 33 + AT_WARPS * 304) * 4;
    int smem_merge = 256 * 64 * 4;
    cudaFuncSetAttribute(kernAttn,  cudaFuncAttributeMaxDynamicSharedMemorySize, smem_attn);
    cudaFuncSetAttribute(kernMerge, cudaFuncAttributeMaxDynamicSharedMemorySize, smem_merge);

    kernA<<<dim3(19, 25, 4), 256>>>(x);
    kernB<<<dim3(12, 938), 256>>>(w_qkv, b_qkv);
    kernAttn<<<BVH, AT_THREADS, smem_attn>>>(bias_table);
    kernMerge<<<15000, 256, smem_merge>>>(w_merge, b_merge, out);
}

// round 5
// speedup vs baseline: 1.4807x; 1.4807x over previous
#include <cuda_runtime.h>

#define NN 4
#define CC 64
#define VV 25
#define TT 300
#define MM 2
#define HH 8
#define HD 32
#define EE 256
#define ROWS 60000   /* NN*MM*VV*TT */
#define BVH 1600     /* (NN*MM*VV) * HH = 200*8 */

#define AT_THREADS 512
#define AT_WARPS 16

// ---------------- device scratch (no allocations allowed) ----------------
__device__ float g_xt[(size_t)ROWS * CC];     // rows x 64
__device__ float g_q [(size_t)ROWS * EE];     // rows x 256
__device__ float g_k [(size_t)ROWS * EE];     // pre-scaled by 1/16
__device__ float g_v [(size_t)ROWS * EE];
__device__ float g_attn[(size_t)ROWS * EE];

// ---------------------------------------------------------------------------
// Kernel A: transpose x (N,C,V,T,M) -> g_xt[row][c], row = ((n*2+m)*V+v)*T+t
// ---------------------------------------------------------------------------
__global__ __launch_bounds__(256) void kernA(const float* __restrict__ x) {
    __shared__ float sm[64][33];
    int tm0 = blockIdx.x * 32;
    int v   = blockIdx.y;
    int n   = blockIdx.z;
    int tid  = threadIdx.x;
    int lane = tid & 31;
    int crow = tid >> 5;
#pragma unroll
    for (int kk = 0; kk < 8; kk++) {
        int c  = crow + (kk << 3);
        int tm = tm0 + lane;
        float val = 0.f;
        if (tm < 600) val = x[((size_t)(n * CC + c) * VV + v) * 600 + tm];
        sm[c][lane] = val;
    }
    __syncthreads();
    int c2 = tid & 63;
    int jb = tid >> 6;
#pragma unroll
    for (int kk = 0; kk < 8; kk++) {
        int j  = jb + (kk << 2);
        int tm = tm0 + j;
        if (tm < 600) {
            int t = tm >> 1, m = tm & 1;
            size_t row = ((size_t)((n * 2 + m) * VV + v)) * TT + t;
            g_xt[row * CC + c2] = sm[c2][j];
        }
    }
}

// ---------------------------------------------------------------------------
// Kernel B: qkv = xt @ w_qkv + b_qkv   (60000 x 64 x 768)
// ---------------------------------------------------------------------------
__global__ __launch_bounds__(256) void kernB(const float* __restrict__ w,
                                             const float* __restrict__ b) {
    __shared__ float sx[64 * 68];
    __shared__ float sw[64 * 68];
    int tid = threadIdx.x;
    int c0 = blockIdx.x * 64;
    int r0 = blockIdx.y * 64;
#pragma unroll
    for (int p = 0; p < 16; p++) {
        int idx = tid + p * 256;
        int a = idx >> 6;
        int e = idx & 63;
        int row = r0 + a;
        float vx = 0.f;
        if (row < ROWS) vx = g_xt[(size_t)row * CC + e];
        sx[e * 68 + a] = vx;
        sw[a * 68 + e] = w[(size_t)a * 768 + c0 + e];
    }
    __syncthreads();
    int tx = tid & 15, ty = tid >> 4;
    float acc[4][4];
#pragma unroll
    for (int i = 0; i < 4; i++)
#pragma unroll
        for (int j = 0; j < 4; j++)
            acc[i][j] = b[c0 + tx * 4 + j];
#pragma unroll
    for (int e = 0; e < 64; e++) {
        float4 a4 = *(const float4*)&sx[e * 68 + ty * 4];
        float4 b4 = *(const float4*)&sw[e * 68 + tx * 4];
        float av[4] = {a4.x, a4.y, a4.z, a4.w};
        float bv[4] = {b4.x, b4.y, b4.z, b4.w};
#pragma unroll
        for (int i = 0; i < 4; i++)
#pragma unroll
            for (int j = 0; j < 4; j++)
                acc[i][j] = fmaf(av[i], bv[j], acc[i][j]);
    }
#pragma unroll
    for (int i = 0; i < 4; i++) {
        int row = r0 + ty * 4 + i;
        if (row < ROWS) {
#pragma unroll
            for (int j = 0; j < 4; j++) {
                int col = c0 + tx * 4 + j;
                float val = acc[i][j];
                if (col < 256)      g_q[(size_t)row * EE + col] = val;
                else if (col < 512) g_k[(size_t)row * EE + col - 256] = val * 0.0625f;
                else                g_v[(size_t)row * EE + col - 512] = val;
            }
        }
    }
}

// ---------------------------------------------------------------------------
// Kernel Attn: one block per (bv, h). K/bias at stride 36 (float4-aligned,
// conflict-free LDS.128), V at stride 32. Each warp handles 2 query rows per
// pass (l0 even, l1=l0+1) sharing K and V shared-memory reads.
// score_j(l) = sum_d q[l][d] * (K[j][d] + bias[l+299-j][d])   (K pre-scaled)
// ---------------------------------------------------------------------------
__global__ __launch_bounds__(AT_THREADS) void kernAttn(const float* __restrict__ bias_table) {
    extern __shared__ float smem[];
    float* sk = smem;                        // 300*36
    float* sv = sk + 300 * 36;               // 300*32
    float* sb = sv + 300 * 32;               // 599*36
    float* sp = sb + 599 * 36;               // 16 warps * 2 rows * 304
    int head = blockIdx.x;
    int bv = head >> 3;
    int h  = head & 7;
    size_t row0 = (size_t)bv * TT;
    int tid = threadIdx.x;

    // fill K (stride 36) and V (stride 32)
    for (int idx = tid; idx < TT * HD; idx += AT_THREADS) {
        int j = idx >> 5, d = idx & 31;
        size_t g = (row0 + j) * EE + h * HD + d;
        sk[j * 36 + d] = g_k[g];
        sv[j * 32 + d] = g_v[g];
    }
    // fill bias table (stride 36)
    for (int idx = tid; idx < 599 * HD; idx += AT_THREADS) {
        int r = idx >> 5, d = idx & 31;
        sb[r * 36 + d] = bias_table[idx];
    }
    __syncthreads();

    int w = tid >> 5, lane = tid & 31;
    float* pw0 = sp + w * 608;
    float* pw1 = pw0 + 304;

    for (int l0 = w * 2; l0 < TT; l0 += 2 * AT_WARPS) {
        int l1 = l0 + 1;   // TT even -> always valid
        // load 2 query rows into registers
        const float4* q0g = (const float4*)(g_q + (row0 + l0) * EE + h * HD);
        const float4* q1g = (const float4*)(g_q + (row0 + l1) * EE + h * HD);
        float4 qa0[8], qa1[8];
#pragma unroll
        for (int d4 = 0; d4 < 8; d4++) { qa0[d4] = __ldg(q0g + d4); qa1[d4] = __ldg(q1g + d4); }

        float acc0[10], acc1[10];
#pragma unroll
        for (int jj = 0; jj < 10; jj++) {
            int j = lane + (jj << 5);
            bool valid = (j < TT);
            int jc = valid ? j : (TT - 1);
            const float4* kp  = (const float4*)(sk + jc * 36);
            const float4* b0p = (const float4*)(sb + (l0 + 299 - jc) * 36);
            const float4* b1p = b0p + 9;   // +36 floats = bias row for l1
            float a0 = 0.f, a1 = 0.f;
#pragma unroll
            for (int d4 = 0; d4 < 8; d4++) {
                float4 k4  = kp[d4];
                float4 b04 = b0p[d4];
                float4 b14 = b1p[d4];
                float4 q0 = qa0[d4], q1 = qa1[d4];
                a0 = fmaf(q0.x, k4.x, a0); a0 = fmaf(q0.y, k4.y, a0);
                a0 = fmaf(q0.z, k4.z, a0); a0 = fmaf(q0.w, k4.w, a0);
                a0 = fmaf(q0.x, b04.x, a0); a0 = fmaf(q0.y, b04.y, a0);
                a0 = fmaf(q0.z, b04.z, a0); a0 = fmaf(q0.w, b04.w, a0);
                a1 = fmaf(q1.x, k4.x, a1); a1 = fmaf(q1.y, k4.y, a1);
                a1 = fmaf(q1.z, k4.z, a1); a1 = fmaf(q1.w, k4.w, a1);
                a1 = fmaf(q1.x, b14.x, a1); a1 = fmaf(q1.y, b14.y, a1);
                a1 = fmaf(q1.z, b14.z, a1); a1 = fmaf(q1.w, b14.w, a1);
            }
            acc0[jj] = valid ? a0 : -3.0e38f;
            acc1[jj] = valid ? a1 : -3.0e38f;
        }

        // softmax row 0
        float mx0 = acc0[0], mx1 = acc1[0];
#pragma unroll
        for (int jj = 1; jj < 10; jj++) { mx0 = fmaxf(mx0, acc0[jj]); mx1 = fmaxf(mx1, acc1[jj]); }
#pragma unroll
        for (int off = 16; off > 0; off >>= 1) {
            mx0 = fmaxf(mx0, __shfl_xor_sync(0xffffffffu, mx0, off));
            mx1 = fmaxf(mx1, __shfl_xor_sync(0xffffffffu, mx1, off));
        }
        float s0 = 0.f, s1 = 0.f;
#pragma unroll
        for (int jj = 0; jj < 10; jj++) {
            int j = lane + (jj << 5);
            float e0 = (j < TT) ? __expf(acc0[jj] - mx0) : 0.f;
            float e1 = (j < TT) ? __expf(acc1[jj] - mx1) : 0.f;
            acc0[jj] = e0; acc1[jj] = e1;
            s0 += e0; s1 += e1;
        }
#pragma unroll
        for (int off = 16; off > 0; off >>= 1) {
            s0 += __shfl_xor_sync(0xffffffffu, s0, off);
            s1 += __shfl_xor_sync(0xffffffffu, s1, off);
        }
        float inv0 = 1.0f / s0, inv1 = 1.0f / s1;
#pragma unroll
        for (int jj = 0; jj < 10; jj++) {
            int j = lane + (jj << 5);
            if (j < TT) { pw0[j] = acc0[jj] * inv0; pw1[j] = acc1[jj] * inv1; }
        }
        __syncwarp();

        // PV: lane = d, shared V reads for both rows
        float o0 = 0.f, o1 = 0.f;
        const float4* p04 = (const float4*)pw0;
        const float4* p14 = (const float4*)pw1;
#pragma unroll 5
        for (int j4 = 0; j4 < 75; j4++) {
            float4 p0 = p04[j4];
            float4 p1 = p14[j4];
            int jb = j4 << 2;
            float v0 = sv[(jb + 0) * 32 + lane];
            float v1 = sv[(jb + 1) * 32 + lane];
            float v2 = sv[(jb + 2) * 32 + lane];
            float v3 = sv[(jb + 3) * 32 + lane];
            o0 = fmaf(p0.x, v0, o0); o1 = fmaf(p1.x, v0, o1);
            o0 = fmaf(p0.y, v1, o0); o1 = fmaf(p1.y, v1, o1);
            o0 = fmaf(p0.z, v2, o0); o1 = fmaf(p1.z, v2, o1);
            o0 = fmaf(p0.w, v3, o0); o1 = fmaf(p1.w, v3, o1);
        }
        g_attn[(row0 + l0) * EE + h * HD + lane] = o0;
        g_attn[(row0 + l1) * EE + h * HD + lane] = o1;
        __syncwarp();
    }
}

// ---------------------------------------------------------------------------
// Kernel Merge: tiled GEMM out = attn @ w_merge + b_merge (60000 x 256 x 64),
// 64x64 block tiles, 4x4 register microtiles, K-chunks of 64 through smem.
// Scattered scatter-store to (N,C,V,T,M) at the end.
// ---------------------------------------------------------------------------
__global__ __launch_bounds__(256) void kernMerge(const float* __restrict__ wm,
                                                 const float* __restrict__ bm,
                                                 float* __restrict__ out) {
    __shared__ float sa[64 * 68];   // sa[e*68 + r] (attn chunk, transposed)
    __shared__ float sw[64 * 68];   // sw[e*68 + c]
    int tid = threadIdx.x;
    int r0 = blockIdx.x * 64;
    int tx = tid & 15, ty = tid >> 4;

    float acc[4][4];
#pragma unroll
    for (int i = 0; i < 4; i++)
#pragma unroll
        for (int j = 0; j < 4; j++)
            acc[i][j] = bm[tx * 4 + j];

    for (int e0 = 0; e0 < 256; e0 += 64) {
        __syncthreads();
#pragma unroll
        for (int p = 0; p < 16; p++) {
            int idx = tid + p * 256;
            int a = idx >> 6;
            int e = idx & 63;
            int row = r0 + a;
            float va = 0.f;
            if (row < ROWS) va = g_attn[(size_t)row * EE + e0 + e];
            sa[e * 68 + a] = va;
            sw[a * 68 + e] = wm[(size_t)(e0 + a) * CC + e];
        }
        __syncthreads();
#pragma unroll
        for (int e = 0; e < 64; e++) {
            float4 a4 = *(const float4*)&sa[e * 68 + ty * 4];
            float4 b4 = *(const float4*)&sw[e * 68 + tx * 4];
            float av[4] = {a4.x, a4.y, a4.z, a4.w};
            float bv[4] = {b4.x, b4.y, b4.z, b4.w};
#pragma unroll
            for (int i = 0; i < 4; i++)
#pragma unroll
                for (int j = 0; j < 4; j++)
                    acc[i][j] = fmaf(av[i], bv[j], acc[i][j]);
        }
    }
#pragma unroll
    for (int i = 0; i < 4; i++) {
        int row = r0 + ty * 4 + i;
        if (row < ROWS) {
            int t  = row % 300;
            int vv = row / 300;
            int v  = vv % 25;
            int nm = vv / 25;
            int m  = nm & 1;
            int n  = nm >> 1;
#pragma unroll
            for (int j = 0; j < 4; j++) {
                int c = tx * 4 + j;
                out[(((size_t)(n * CC + c) * VV + v) * TT + t) * MM + m] = acc[i][j];
            }
        }
    }
}

// ---------------------------------------------------------------------------
extern "C" void kernel_launch(void* const* d_in, const int* in_sizes, int n_in,
                              void* d_out, int out_size) {
    const float* x          = (const float*)d_in[0];
    const float* w_qkv      = (const float*)d_in[1];
    const float* b_qkv      = (const float*)d_in[2];
    const float* w_merge    = (const float*)d_in[3];
    const float* b_merge    = (const float*)d_in[4];
    const float* bias_table = (const float*)d_in[5];
    float* out = (float*)d_out;

    int smem_attn = (300 * 36 + 300 * 32 + 599 * 36 + AT_WARPS * 608) * 4;
    cudaFuncSetAttribute(kernAttn, cudaFuncAttributeMaxDynamicSharedMemorySize, smem_attn);

    kernA<<<dim3(19, 25, 4), 256>>>(x);
    kernB<<<dim3(12, 938), 256>>>(w_qkv, b_qkv);
    kernAttn<<<BVH, AT_THREADS, smem_attn>>>(bias_table);
    kernMerge<<<938, 256>>>(w_merge, b_merge, out);
}

// round 6
// speedup vs baseline: 1.9349x; 1.3067x over previous
#include <cuda_runtime.h>

#define NN 4
#define CC 64
#define VV 25
#define TT 300
#define MM 2
#define HH 8
#define HD 32
#define EE 256
#define ROWS 60000   /* NN*MM*VV*TT */
#define BVH 1600     /* (NN*MM*VV) * HH */

// ---------------- device scratch (no allocations allowed) ----------------
__device__ float g_xt[(size_t)ROWS * CC];
__device__ float g_q [(size_t)ROWS * EE];
__device__ float g_k [(size_t)ROWS * EE];     // pre-scaled by 1/16
__device__ float g_v [(size_t)ROWS * EE];
__device__ float g_attn[(size_t)ROWS * EE];

__device__ __forceinline__ float tf32f(float x) {
    unsigned u;
    asm("cvt.rna.tf32.f32 %0, %1;" : "=r"(u) : "f"(x));
    return __uint_as_float(u);
}

// ---------------------------------------------------------------------------
// Kernel A: transpose x (N,C,V,T,M) -> g_xt[row][c]
// ---------------------------------------------------------------------------
__global__ __launch_bounds__(256) void kernA(const float* __restrict__ x) {
    __shared__ float sm[64][33];
    int tm0 = blockIdx.x * 32;
    int v   = blockIdx.y;
    int n   = blockIdx.z;
    int tid  = threadIdx.x;
    int lane = tid & 31;
    int crow = tid >> 5;
#pragma unroll
    for (int kk = 0; kk < 8; kk++) {
        int c  = crow + (kk << 3);
        int tm = tm0 + lane;
        float val = 0.f;
        if (tm < 600) val = x[((size_t)(n * CC + c) * VV + v) * 600 + tm];
        sm[c][lane] = val;
    }
    __syncthreads();
    int c2 = tid & 63;
    int jb = tid >> 6;
#pragma unroll
    for (int kk = 0; kk < 8; kk++) {
        int j  = jb + (kk << 2);
        int tm = tm0 + j;
        if (tm < 600) {
            int t = tm >> 1, m = tm & 1;
            size_t row = ((size_t)((n * 2 + m) * VV + v)) * TT + t;
            g_xt[row * CC + c2] = sm[c2][j];
        }
    }
}

// ---------------------------------------------------------------------------
// Kernel B: qkv = xt @ w_qkv + b_qkv   (60000 x 64 x 768)
// ---------------------------------------------------------------------------
__global__ __launch_bounds__(256) void kernB(const float* __restrict__ w,
                                             const float* __restrict__ b) {
    __shared__ float sx[64 * 68];
    __shared__ float sw[64 * 68];
    int tid = threadIdx.x;
    int c0 = blockIdx.x * 64;
    int r0 = blockIdx.y * 64;
#pragma unroll
    for (int p = 0; p < 16; p++) {
        int idx = tid + p * 256;
        int a = idx >> 6;
        int e = idx & 63;
        int row = r0 + a;
        float vx = 0.f;
        if (row < ROWS) vx = g_xt[(size_t)row * CC + e];
        sx[e * 68 + a] = vx;
        sw[a * 68 + e] = w[(size_t)a * 768 + c0 + e];
    }
    __syncthreads();
    int tx = tid & 15, ty = tid >> 4;
    float acc[4][4];
#pragma unroll
    for (int i = 0; i < 4; i++)
#pragma unroll
        for (int j = 0; j < 4; j++)
            acc[i][j] = b[c0 + tx * 4 + j];
#pragma unroll
    for (int e = 0; e < 64; e++) {
        float4 a4 = *(const float4*)&sx[e * 68 + ty * 4];
        float4 b4 = *(const float4*)&sw[e * 68 + tx * 4];
        float av[4] = {a4.x, a4.y, a4.z, a4.w};
        float bv[4] = {b4.x, b4.y, b4.z, b4.w};
#pragma unroll
        for (int i = 0; i < 4; i++)
#pragma unroll
            for (int j = 0; j < 4; j++)
                acc[i][j] = fmaf(av[i], bv[j], acc[i][j]);
    }
#pragma unroll
    for (int i = 0; i < 4; i++) {
        int row = r0 + ty * 4 + i;
        if (row < ROWS) {
#pragma unroll
            for (int j = 0; j < 4; j++) {
                int col = c0 + tx * 4 + j;
                float val = acc[i][j];
                if (col < 256)      g_q[(size_t)row * EE + col] = val;
                else if (col < 512) g_k[(size_t)row * EE + col - 256] = val * 0.0625f;
                else                g_v[(size_t)row * EE + col - 512] = val;
            }
        }
    }
}

// ---------------------------------------------------------------------------
// Kernel Attn (tf32 mma): block per (bv,h).
// S = Q K^T and R = Q B^T via mma.m16n8k8.tf32; score = S[l][j] + R[l][l+299-j].
// l-tiles of 16 rows; softmax warp-per-row; PV fp32, 4 warps x 4 rows.
// smem strides: tf32 operands 36 (conflict-free frags), sS 308, sR 324.
// ---------------------------------------------------------------------------
__global__ __launch_bounds__(512) void kernAttn(const float* __restrict__ bias_table) {
    extern __shared__ float smem[];
    float* sb = smem;               // 608 x 36 (tf32 bits)
    float* sk = sb + 608 * 36;      // 304 x 36 (tf32 bits)
    float* sv = sk + 304 * 36;      // 300 x 32 fp32
    float* sq = sv + 300 * 32;      // 16 x 36 (tf32 bits)
    float* sS = sq + 16 * 36;       // 16 x 308 (scores, then probs)
    float* sR = sS + 16 * 308;      // 16 x 324

    int head = blockIdx.x;
    int bv = head >> 3;
    int h  = head & 7;
    size_t row0 = (size_t)bv * TT;
    int tid = threadIdx.x;
    int w = tid >> 5, lane = tid & 31;
    int gid = lane >> 2, tig = lane & 3;

    // fill K (tf32, padded rows 300..303 = 0) and V
    for (int idx = tid; idx < 304 * 32; idx += 512) {
        int j = idx >> 5, d = idx & 31;
        float kv = 0.f;
        if (j < 300) {
            size_t g = (row0 + j) * EE + h * HD + d;
            kv = g_k[g];
            sv[j * 32 + d] = g_v[g];
        }
        sk[j * 36 + d] = tf32f(kv);
    }
    // fill bias table (tf32, padded rows 599..607 = 0)
    for (int idx = tid; idx < 608 * 32; idx += 512) {
        int r = idx >> 5, d = idx & 31;
        float bb = (r < 599) ? bias_table[r * 32 + d] : 0.f;
        sb[r * 36 + d] = tf32f(bb);
    }

    for (int l0 = 0; l0 < TT; l0 += 16) {
        __syncthreads();   // prev tile's phase1 (sq) + PV (sS) complete
        // stage q tile (16 x 32), clamped rows
        {
            int r = tid >> 5, d = tid & 31;     // tid < 512 -> r < 16
            int l = l0 + r; if (l > 299) l = 299;
            sq[r * 36 + d] = tf32f(g_q[(row0 + l) * EE + h * HD + d]);
        }
        __syncthreads();

        // A fragments (shared across all jobs of this tile)
        unsigned afr[4][4];
#pragma unroll
        for (int ks = 0; ks < 4; ks++) {
            afr[ks][0] = __float_as_uint(sq[gid * 36 + ks * 8 + tig]);
            afr[ks][1] = __float_as_uint(sq[(gid + 8) * 36 + ks * 8 + tig]);
            afr[ks][2] = __float_as_uint(sq[gid * 36 + ks * 8 + tig + 4]);
            afr[ks][3] = __float_as_uint(sq[(gid + 8) * 36 + ks * 8 + tig + 4]);
        }

        // phase1: 38 S n-tiles + 40 R n-tiles over 16 warps
        for (int jb = w; jb < 78; jb += 16) {
            float c0 = 0.f, c1 = 0.f, c2 = 0.f, c3 = 0.f;
            const float* bsrc;
            float* dst;
            int n0, dstride;
            if (jb < 38) {
                n0 = jb * 8;
                bsrc = sk + (n0 + gid) * 36;
                dst = sS; dstride = 308;
            } else {
                n0 = (jb - 38) * 8;
                bsrc = sb + (l0 + n0 + gid) * 36;
                dst = sR; dstride = 324;
            }
#pragma unroll
            for (int ks = 0; ks < 4; ks++) {
                unsigned b0 = __float_as_uint(bsrc[ks * 8 + tig]);
                unsigned b1 = __float_as_uint(bsrc[ks * 8 + tig + 4]);
                asm volatile(
                    "mma.sync.aligned.m16n8k8.row.col.f32.tf32.tf32.f32 "
                    "{%0,%1,%2,%3}, {%4,%5,%6,%7}, {%8,%9}, {%0,%1,%2,%3};\n"
                    : "+f"(c0), "+f"(c1), "+f"(c2), "+f"(c3)
                    : "r"(afr[ks][0]), "r"(afr[ks][1]), "r"(afr[ks][2]), "r"(afr[ks][3]),
                      "r"(b0), "r"(b1));
            }
            float* p0 = dst + gid * dstride + n0 + 2 * tig;
            *(float2*)p0 = make_float2(c0, c1);
            *(float2*)(p0 + 8 * dstride) = make_float2(c2, c3);
        }
        __syncthreads();

        // phase2: softmax, warp w handles row l0+w
        {
            int l = l0 + w;
            if (l < TT) {
                float sc[10];
#pragma unroll
                for (int jj = 0; jj < 10; jj++) {
                    int j = lane + (jj << 5);
                    if (j < TT)
                        sc[jj] = sS[w * 308 + j] + sR[w * 324 + (w + 299 - j)];
                    else
                        sc[jj] = -3.0e38f;
                }
                float mx = sc[0];
#pragma unroll
                for (int jj = 1; jj < 10; jj++) mx = fmaxf(mx, sc[jj]);
#pragma unroll
                for (int off = 16; off > 0; off >>= 1)
                    mx = fmaxf(mx, __shfl_xor_sync(0xffffffffu, mx, off));
                float s = 0.f;
#pragma unroll
                for (int jj = 0; jj < 10; jj++) {
                    int j = lane + (jj << 5);
                    float e = (j < TT) ? __expf(sc[jj] - mx) : 0.f;
                    sc[jj] = e;
                    s += e;
                }
#pragma unroll
                for (int off = 16; off > 0; off >>= 1)
                    s += __shfl_xor_sync(0xffffffffu, s, off);
                float inv = 1.0f / s;
#pragma unroll
                for (int jj = 0; jj < 10; jj++) {
                    int j = lane + (jj << 5);
                    if (j < 304) sS[w * 308 + j] = (j < TT) ? sc[jj] * inv : 0.f;
                }
            }
        }
        __syncthreads();

        // phase3: PV, warps 0..3, 4 rows each, shared V reads
        if (w < 4) {
            float o0 = 0.f, o1 = 0.f, o2 = 0.f, o3 = 0.f;
            const float4* pr0 = (const float4*)(sS + (4 * w + 0) * 308);
            const float4* pr1 = (const float4*)(sS + (4 * w + 1) * 308);
            const float4* pr2 = (const float4*)(sS + (4 * w + 2) * 308);
            const float4* pr3 = (const float4*)(sS + (4 * w + 3) * 308);
#pragma unroll 5
            for (int j4 = 0; j4 < 75; j4++) {
                float4 p0 = pr0[j4], p1 = pr1[j4], p2 = pr2[j4], p3 = pr3[j4];
                int jb2 = j4 << 2;
                float v0 = sv[(jb2 + 0) * 32 + lane];
                float v1 = sv[(jb2 + 1) * 32 + lane];
                float v2 = sv[(jb2 + 2) * 32 + lane];
                float v3 = sv[(jb2 + 3) * 32 + lane];
                o0 = fmaf(p0.x, v0, o0); o1 = fmaf(p1.x, v0, o1);
                o2 = fmaf(p2.x, v0, o2); o3 = fmaf(p3.x, v0, o3);
                o0 = fmaf(p0.y, v1, o0); o1 = fmaf(p1.y, v1, o1);
                o2 = fmaf(p2.y, v1, o2); o3 = fmaf(p3.y, v1, o3);
                o0 = fmaf(p0.z, v2, o0); o1 = fmaf(p1.z, v2, o1);
                o2 = fmaf(p2.z, v2, o2); o3 = fmaf(p3.z, v2, o3);
                o0 = fmaf(p0.w, v3, o0); o1 = fmaf(p1.w, v3, o1);
                o2 = fmaf(p2.w, v3, o2); o3 = fmaf(p3.w, v3, o3);
            }
            int lb = l0 + 4 * w;
            float oo[4] = {o0, o1, o2, o3};
#pragma unroll
            for (int i = 0; i < 4; i++) {
                int l = lb + i;
                if (l < TT) g_attn[(row0 + l) * EE + h * HD + lane] = oo[i];
            }
        }
    }
}

// ---------------------------------------------------------------------------
// Kernel Merge: tiled GEMM out = attn @ w_merge + b_merge, scatter-store.
// ---------------------------------------------------------------------------
__global__ __launch_bounds__(256) void kernMerge(const float* __restrict__ wm,
                                                 const float* __restrict__ bm,
                                                 float* __restrict__ out) {
    __shared__ float sa[64 * 68];
    __shared__ float sw[64 * 68];
    int tid = threadIdx.x;
    int r0 = blockIdx.x * 64;
    int tx = tid & 15, ty = tid >> 4;

    float acc[4][4];
#pragma unroll
    for (int i = 0; i < 4; i++)
#pragma unroll
        for (int j = 0; j < 4; j++)
            acc[i][j] = bm[tx * 4 + j];

    for (int e0 = 0; e0 < 256; e0 += 64) {
        __syncthreads();
#pragma unroll
        for (int p = 0; p < 16; p++) {
            int idx = tid + p * 256;
            int a = idx >> 6;
            int e = idx & 63;
            int row = r0 + a;
            float va = 0.f;
            if (row < ROWS) va = g_attn[(size_t)row * EE + e0 + e];
            sa[e * 68 + a] = va;
            sw[a * 68 + e] = wm[(size_t)(e0 + a) * CC + e];
        }
        __syncthreads();
#pragma unroll
        for (int e = 0; e < 64; e++) {
            float4 a4 = *(const float4*)&sa[e * 68 + ty * 4];
            float4 b4 = *(const float4*)&sw[e * 68 + tx * 4];
            float av[4] = {a4.x, a4.y, a4.z, a4.w};
            float bv[4] = {b4.x, b4.y, b4.z, b4.w};
#pragma unroll
            for (int i = 0; i < 4; i++)
#pragma unroll
                for (int j = 0; j < 4; j++)
                    acc[i][j] = fmaf(av[i], bv[j], acc[i][j]);
        }
    }
#pragma unroll
    for (int i = 0; i < 4; i++) {
        int row = r0 + ty * 4 + i;
        if (row < ROWS) {
            int t  = row % 300;
            int vv = row / 300;
            int v  = vv % 25;
            int nm = vv / 25;
            int m  = nm & 1;
            int n  = nm >> 1;
#pragma unroll
            for (int j = 0; j < 4; j++) {
                int c = tx * 4 + j;
                out[(((size_t)(n * CC + c) * VV + v) * TT + t) * MM + m] = acc[i][j];
            }
        }
    }
}

// ---------------------------------------------------------------------------
extern "C" void kernel_launch(void* const* d_in, const int* in_sizes, int n_in,
                              void* d_out, int out_size) {
    const float* x          = (const float*)d_in[0];
    const float* w_qkv      = (const float*)d_in[1];
    const float* b_qkv      = (const float*)d_in[2];
    const float* w_merge    = (const float*)d_in[3];
    const float* b_merge    = (const float*)d_in[4];
    const float* bias_table = (const float*)d_in[5];
    float* out = (float*)d_out;

    int smem_attn = (608 * 36 + 304 * 36 + 300 * 32 + 16 * 36 + 16 * 308 + 16 * 324) * 4;
    cudaFuncSetAttribute(kernAttn, cudaFuncAttributeMaxDynamicSharedMemorySize, smem_attn);

    kernA<<<dim3(19, 25, 4), 256>>>(x);
    kernB<<<dim3(12, 938), 256>>>(w_qkv, b_qkv);
    kernAttn<<<BVH, 512, smem_attn>>>(bias_table);
    kernMerge<<<938, 256>>>(w_merge, b_merge, out);
}

// round 7
// speedup vs baseline: 2.8192x; 1.4570x over previous
#include <cuda_runtime.h>

#define NN 4
#define CC 64
#define VV 25
#define TT 300
#define MM 2
#define HH 8
#define HD 32
#define EE 256
#define ROWS 60000   /* NN*MM*VV*TT */
#define BVH 1600     /* (NN*MM*VV) * HH */

// ---------------- device scratch (no allocations allowed) ----------------
__device__ float g_xt[(size_t)ROWS * CC];
__device__ float g_q [(size_t)ROWS * EE];
__device__ float g_k [(size_t)ROWS * EE];     // pre-scaled by 1/16
__device__ float g_v [(size_t)ROWS * EE];
__device__ float g_attn[(size_t)ROWS * EE];

__device__ __forceinline__ float tf32f(float x) {
    unsigned u;
    asm("cvt.rna.tf32.f32 %0, %1;" : "=r"(u) : "f"(x));
    return __uint_as_float(u);
}

// ---------------------------------------------------------------------------
// Kernel A: transpose x (N,C,V,T,M) -> g_xt[row][c]
// ---------------------------------------------------------------------------
__global__ __launch_bounds__(256) void kernA(const float* __restrict__ x) {
    __shared__ float sm[64][33];
    int tm0 = blockIdx.x * 32;
    int v   = blockIdx.y;
    int n   = blockIdx.z;
    int tid  = threadIdx.x;
    int lane = tid & 31;
    int crow = tid >> 5;
#pragma unroll
    for (int kk = 0; kk < 8; kk++) {
        int c  = crow + (kk << 3);
        int tm = tm0 + lane;
        float val = 0.f;
        if (tm < 600) val = x[((size_t)(n * CC + c) * VV + v) * 600 + tm];
        sm[c][lane] = val;
    }
    __syncthreads();
    int c2 = tid & 63;
    int jb = tid >> 6;
#pragma unroll
    for (int kk = 0; kk < 8; kk++) {
        int j  = jb + (kk << 2);
        int tm = tm0 + j;
        if (tm < 600) {
            int t = tm >> 1, m = tm & 1;
            size_t row = ((size_t)((n * 2 + m) * VV + v)) * TT + t;
            g_xt[row * CC + c2] = sm[c2][j];
        }
    }
}

// ---------------------------------------------------------------------------
// Kernel B: qkv = xt @ w_qkv + b_qkv   (60000 x 64 x 768)
// ---------------------------------------------------------------------------
__global__ __launch_bounds__(256) void kernB(const float* __restrict__ w,
                                             const float* __restrict__ b) {
    __shared__ float sx[64 * 68];
    __shared__ float sw[64 * 68];
    int tid = threadIdx.x;
    int c0 = blockIdx.x * 64;
    int r0 = blockIdx.y * 64;
#pragma unroll
    for (int p = 0; p < 16; p++) {
        int idx = tid + p * 256;
        int a = idx >> 6;
        int e = idx & 63;
        int row = r0 + a;
        float vx = 0.f;
        if (row < ROWS) vx = g_xt[(size_t)row * CC + e];
        sx[e * 68 + a] = vx;
        sw[a * 68 + e] = w[(size_t)a * 768 + c0 + e];
    }
    __syncthreads();
    int tx = tid & 15, ty = tid >> 4;
    float acc[4][4];
#pragma unroll
    for (int i = 0; i < 4; i++)
#pragma unroll
        for (int j = 0; j < 4; j++)
            acc[i][j] = b[c0 + tx * 4 + j];
#pragma unroll
    for (int e = 0; e < 64; e++) {
        float4 a4 = *(const float4*)&sx[e * 68 + ty * 4];
        float4 b4 = *(const float4*)&sw[e * 68 + tx * 4];
        float av[4] = {a4.x, a4.y, a4.z, a4.w};
        float bv[4] = {b4.x, b4.y, b4.z, b4.w};
#pragma unroll
        for (int i = 0; i < 4; i++)
#pragma unroll
            for (int j = 0; j < 4; j++)
                acc[i][j] = fmaf(av[i], bv[j], acc[i][j]);
    }
#pragma unroll
    for (int i = 0; i < 4; i++) {
        int row = r0 + ty * 4 + i;
        if (row < ROWS) {
#pragma unroll
            for (int j = 0; j < 4; j++) {
                int col = c0 + tx * 4 + j;
                float val = acc[i][j];
                if (col < 256)      g_q[(size_t)row * EE + col] = val;
                else if (col < 512) g_k[(size_t)row * EE + col - 256] = val * 0.0625f;
                else                g_v[(size_t)row * EE + col - 512] = val;
            }
        }
    }
}

// ---------------------------------------------------------------------------
// Kernel Attn (all-tensor tf32): block per (bv,h), 1024 threads, 32-row tiles.
//  phase R: R-mma jobs scatter-STORE bias scores into sS at j = lr+299-r
//           (bijection -> exactly one store per (lr, j<=299), no init needed)
//  phase S: S-mma jobs read-add-write Q.K^T into sS
//  softmax: warp-per-row, probs written back tf32-rounded (in place)
//  PV:      tensor mma P @ V (V tf32 at stride 40 -> conflict-free B frags)
// ---------------------------------------------------------------------------
__global__ __launch_bounds__(1024, 1) void kernAttn(const float* __restrict__ bias_table) {
    extern __shared__ float smem[];
    float* sb = smem;                    // 624 x 36 (tf32) rows >=599 zero
    float* sk = sb + 624 * 36;           // 304 x 36 (tf32) rows >=300 zero
    float* sv = sk + 304 * 36;           // 304 x 40 (tf32) rows >=300 zero
    float* sq = sv + 304 * 40;           // 32 x 36 (tf32)
    float* sS = sq + 32 * 36;            // 32 x 308 scores -> probs

    int head = blockIdx.x;
    int bv = head >> 3;
    int h  = head & 7;
    size_t row0 = (size_t)bv * TT;
    int tid = threadIdx.x;
    int w = tid >> 5, lane = tid & 31;
    int gid = lane >> 2, tig = lane & 3;

    // fills
    for (int idx = tid; idx < 624 * 32; idx += 1024) {
        int r = idx >> 5, d = idx & 31;
        float bb = (r < 599) ? bias_table[r * 32 + d] : 0.f;
        sb[r * 36 + d] = tf32f(bb);
    }
    for (int idx = tid; idx < 304 * 32; idx += 1024) {
        int j = idx >> 5, d = idx & 31;
        float kv = 0.f, vv = 0.f;
        if (j < 300) {
            size_t g = (row0 + j) * EE + h * HD + d;
            kv = g_k[g];
            vv = g_v[g];
        }
        sk[j * 36 + d] = tf32f(kv);
        sv[j * 40 + d] = tf32f(vv);
    }

    int mt   = w & 1;        // m-tile for phase1 jobs
    int qidx = w >> 1;       // 0..15

    for (int l0 = 0; l0 < TT; l0 += 32) {
        __syncthreads();     // sS free (PV of prev tile done), sq free
        // stage q tile 32 x 32 (clamped rows)
        {
            int r = tid >> 5, d = lane;
            int l = l0 + r; if (l > 299) l = 299;
            sq[r * 36 + d] = tf32f(g_q[(row0 + l) * EE + h * HD + d]);
        }
        __syncthreads();

        // A fragments for this warp's m-tile
        unsigned af[4][4];
        {
            const float* q0 = sq + (mt * 16 + gid) * 36;
            const float* q8 = q0 + 8 * 36;
#pragma unroll
            for (int ks = 0; ks < 4; ks++) {
                af[ks][0] = __float_as_uint(q0[ks * 8 + tig]);
                af[ks][1] = __float_as_uint(q8[ks * 8 + tig]);
                af[ks][2] = __float_as_uint(q0[ks * 8 + tig + 4]);
                af[ks][3] = __float_as_uint(q8[ks * 8 + tig + 4]);
            }
        }

        // ---- phase R: scatter-store rel-position scores ----
        for (int nt = qidx; nt < 42; nt += 16) {
            float c0 = 0.f, c1 = 0.f, c2 = 0.f, c3 = 0.f;
            const float* bsrc = sb + (l0 + 8 * nt + gid) * 36;
#pragma unroll
            for (int ks = 0; ks < 4; ks++) {
                unsigned b0 = __float_as_uint(bsrc[ks * 8 + tig]);
                unsigned b1 = __float_as_uint(bsrc[ks * 8 + tig + 4]);
                asm volatile(
                    "mma.sync.aligned.m16n8k8.row.col.f32.tf32.tf32.f32 "
                    "{%0,%1,%2,%3}, {%4,%5,%6,%7}, {%8,%9}, {%0,%1,%2,%3};\n"
                    : "+f"(c0), "+f"(c1), "+f"(c2), "+f"(c3)
                    : "r"(af[ks][0]), "r"(af[ks][1]), "r"(af[ks][2]), "r"(af[ks][3]),
                      "r"(b0), "r"(b1));
            }
            int lr = mt * 16 + gid;
            int jb = lr + 299 - 8 * nt - 2 * tig;   // col for c0 (row lr)
            if (jb >= 0 && jb < 304)         sS[lr * 308 + jb]           = c0;
            if (jb - 1 >= 0 && jb - 1 < 304) sS[lr * 308 + jb - 1]       = c1;
            int jb8 = jb + 8;                        // col for c2 (row lr+8)
            if (jb8 >= 0 && jb8 < 304)         sS[(lr + 8) * 308 + jb8]     = c2;
            if (jb8 - 1 >= 0 && jb8 - 1 < 304) sS[(lr + 8) * 308 + jb8 - 1] = c3;
        }
        __syncthreads();

        // ---- phase S: add Q.K^T ----
        for (int nt = qidx; nt < 38; nt += 16) {
            float c0 = 0.f, c1 = 0.f, c2 = 0.f, c3 = 0.f;
            const float* bsrc = sk + (8 * nt + gid) * 36;
#pragma unroll
            for (int ks = 0; ks < 4; ks++) {
                unsigned b0 = __float_as_uint(bsrc[ks * 8 + tig]);
                unsigned b1 = __float_as_uint(bsrc[ks * 8 + tig + 4]);
                asm volatile(
                    "mma.sync.aligned.m16n8k8.row.col.f32.tf32.tf32.f32 "
                    "{%0,%1,%2,%3}, {%4,%5,%6,%7}, {%8,%9}, {%0,%1,%2,%3};\n"
                    : "+f"(c0), "+f"(c1), "+f"(c2), "+f"(c3)
                    : "r"(af[ks][0]), "r"(af[ks][1]), "r"(af[ks][2]), "r"(af[ks][3]),
                      "r"(b0), "r"(b1));
            }
            float* p = sS + (mt * 16 + gid) * 308 + 8 * nt + 2 * tig;
            float2 e0 = *(float2*)p;
            e0.x += c0; e0.y += c1;
            *(float2*)p = e0;
            float* p2 = p + 8 * 308;
            float2 e1 = *(float2*)p2;
            e1.x += c2; e1.y += c3;
            *(float2*)p2 = e1;
        }
        __syncthreads();

        // ---- softmax: warp w handles row w ----
        {
            int l = l0 + w;
            float* row = sS + w * 308;
            if (l < TT) {
                float sc[10];
#pragma unroll
                for (int jj = 0; jj < 10; jj++) {
                    int j = lane + (jj << 5);
                    sc[jj] = (j < TT) ? row[j] : -3.0e38f;
                }
                float mx = sc[0];
#pragma unroll
                for (int jj = 1; jj < 10; jj++) mx = fmaxf(mx, sc[jj]);
#pragma unroll
                for (int off = 16; off > 0; off >>= 1)
                    mx = fmaxf(mx, __shfl_xor_sync(0xffffffffu, mx, off));
                float s = 0.f;
#pragma unroll
                for (int jj = 0; jj < 10; jj++) {
                    int j = lane + (jj << 5);
                    float e = (j < TT) ? __expf(sc[jj] - mx) : 0.f;
                    sc[jj] = e;
                    s += e;
                }
#pragma unroll
                for (int off = 16; off > 0; off >>= 1)
                    s += __shfl_xor_sync(0xffffffffu, s, off);
                float inv = 1.0f / s;
#pragma unroll
                for (int jj = 0; jj < 10; jj++) {
                    int j = lane + (jj << 5);
                    if (j < 304) row[j] = (j < TT) ? tf32f(sc[jj] * inv) : 0.f;
                }
            } else {
#pragma unroll
                for (int jj = 0; jj < 10; jj++) {
                    int j = lane + (jj << 5);
                    if (j < 304) row[j] = 0.f;
                }
            }
        }
        __syncthreads();

        // ---- PV: warps 0..7, tensor mma P(16x304) @ V(304x8-tile) ----
        if (w < 8) {
            int pmt = w & 1;
            int n0  = (w >> 1) * 8;
            float c0 = 0.f, c1 = 0.f, c2 = 0.f, c3 = 0.f;
            const float* pa0 = sS + (pmt * 16 + gid) * 308;
            const float* pa8 = pa0 + 8 * 308;
#pragma unroll 2
            for (int ks = 0; ks < 38; ks++) {
                unsigned a0 = __float_as_uint(pa0[ks * 8 + tig]);
                unsigned a1 = __float_as_uint(pa8[ks * 8 + tig]);
                unsigned a2 = __float_as_uint(pa0[ks * 8 + tig + 4]);
                unsigned a3 = __float_as_uint(pa8[ks * 8 + tig + 4]);
                unsigned b0 = __float_as_uint(sv[(ks * 8 + tig) * 40 + n0 + gid]);
                unsigned b1 = __float_as_uint(sv[(ks * 8 + tig + 4) * 40 + n0 + gid]);
                asm volatile(
                    "mma.sync.aligned.m16n8k8.row.col.f32.tf32.tf32.f32 "
                    "{%0,%1,%2,%3}, {%4,%5,%6,%7}, {%8,%9}, {%0,%1,%2,%3};\n"
                    : "+f"(c0), "+f"(c1), "+f"(c2), "+f"(c3)
                    : "r"(a0), "r"(a1), "r"(a2), "r"(a3), "r"(b0), "r"(b1));
            }
            int r1 = l0 + pmt * 16 + gid;
            int d0 = n0 + 2 * tig;
            if (r1 < TT)
                *(float2*)&g_attn[(row0 + r1) * EE + h * HD + d0] = make_float2(c0, c1);
            int r2 = r1 + 8;
            if (r2 < TT)
                *(float2*)&g_attn[(row0 + r2) * EE + h * HD + d0] = make_float2(c2, c3);
        }
    }
}

// ---------------------------------------------------------------------------
// Kernel Merge: tiled GEMM out = attn @ w_merge + b_merge, scatter-store.
// ---------------------------------------------------------------------------
__global__ __launch_bounds__(256) void kernMerge(const float* __restrict__ wm,
                                                 const float* __restrict__ bm,
                                                 float* __restrict__ out) {
    __shared__ float sa[64 * 68];
    __shared__ float sw[64 * 68];
    int tid = threadIdx.x;
    int r0 = blockIdx.x * 64;
    int tx = tid & 15, ty = tid >> 4;

    float acc[4][4];
#pragma unroll
    for (int i = 0; i < 4; i++)
#pragma unroll
        for (int j = 0; j < 4; j++)
            acc[i][j] = bm[tx * 4 + j];

    for (int e0 = 0; e0 < 256; e0 += 64) {
        __syncthreads();
#pragma unroll
        for (int p = 0; p < 16; p++) {
            int idx = tid + p * 256;
            int a = idx >> 6;
            int e = idx & 63;
            int row = r0 + a;
            float va = 0.f;
            if (row < ROWS) va = g_attn[(size_t)row * EE + e0 + e];
            sa[e * 68 + a] = va;
            sw[a * 68 + e] = wm[(size_t)(e0 + a) * CC + e];
        }
        __syncthreads();
#pragma unroll
        for (int e = 0; e < 64; e++) {
            float4 a4 = *(const float4*)&sa[e * 68 + ty * 4];
            float4 b4 = *(const float4*)&sw[e * 68 + tx * 4];
            float av[4] = {a4.x, a4.y, a4.z, a4.w};
            float bv[4] = {b4.x, b4.y, b4.z, b4.w};
#pragma unroll
            for (int i = 0; i < 4; i++)
#pragma unroll
                for (int j = 0; j < 4; j++)
                    acc[i][j] = fmaf(av[i], bv[j], acc[i][j]);
        }
    }
#pragma unroll
    for (int i = 0; i < 4; i++) {
        int row = r0 + ty * 4 + i;
        if (row < ROWS) {
            int t  = row % 300;
            int vv = row / 300;
            int v  = vv % 25;
            int nm = vv / 25;
            int m  = nm & 1;
            int n  = nm >> 1;
#pragma unroll
            for (int j = 0; j < 4; j++) {
                int c = tx * 4 + j;
                out[(((size_t)(n * CC + c) * VV + v) * TT + t) * MM + m] = acc[i][j];
            }
        }
    }
}

// ---------------------------------------------------------------------------
extern "C" void kernel_launch(void* const* d_in, const int* in_sizes, int n_in,
                              void* d_out, int out_size) {
    const float* x          = (const float*)d_in[0];
    const float* w_qkv      = (const float*)d_in[1];
    const float* b_qkv      = (const float*)d_in[2];
    const float* w_merge    = (const float*)d_in[3];
    const float* b_merge    = (const float*)d_in[4];
    const float* bias_table = (const float*)d_in[5];
    float* out = (float*)d_out;

    int smem_attn = (624 * 36 + 304 * 36 + 304 * 40 + 32 * 36 + 32 * 308) * 4;
    cudaFuncSetAttribute(kernAttn, cudaFuncAttributeMaxDynamicSharedMemorySize, smem_attn);

    kernA<<<dim3(19, 25, 4), 256>>>(x);
    kernB<<<dim3(12, 938), 256>>>(w_qkv, b_qkv);
    kernAttn<<<BVH, 1024, smem_attn>>>(bias_table);
    kernMerge<<<938, 256>>>(w_merge, b_merge, out);
}

// round 8
// speedup vs baseline: 3.0047x; 1.0658x over previous
#include <cuda_runtime.h>

#define NN 4
#define CC 64
#define VV 25
#define TT 300
#define MM 2
#define HH 8
#define HD 32
#define EE 256
#define ROWS 60000   /* NN*MM*VV*TT */
#define BVH 1600     /* (NN*MM*VV) * HH */

// ---------------- device scratch (no allocations allowed) ----------------
__device__ float g_xt[(size_t)ROWS * CC];
__device__ float g_q [(size_t)ROWS * EE];
__device__ float g_k [(size_t)ROWS * EE];     // pre-scaled by 1/16
__device__ float g_v [(size_t)ROWS * EE];
__device__ float g_attn[(size_t)ROWS * EE];

__device__ __forceinline__ float tf32f(float x) {
    unsigned u;
    asm("cvt.rna.tf32.f32 %0, %1;" : "=r"(u) : "f"(x));
    return __uint_as_float(u);
}

#define MMA_TF32(c0,c1,c2,c3,a0,a1,a2,a3,b0,b1) \
    asm volatile( \
        "mma.sync.aligned.m16n8k8.row.col.f32.tf32.tf32.f32 " \
        "{%0,%1,%2,%3}, {%4,%5,%6,%7}, {%8,%9}, {%0,%1,%2,%3};\n" \
        : "+f"(c0), "+f"(c1), "+f"(c2), "+f"(c3) \
        : "r"(a0), "r"(a1), "r"(a2), "r"(a3), "r"(b0), "r"(b1))

// ---------------------------------------------------------------------------
// Kernel A: transpose x (N,C,V,T,M) -> g_xt[row][c]
// ---------------------------------------------------------------------------
__global__ __launch_bounds__(256) void kernA(const float* __restrict__ x) {
    __shared__ float sm[64][33];
    int tm0 = blockIdx.x * 32;
    int v   = blockIdx.y;
    int n   = blockIdx.z;
    int tid  = threadIdx.x;
    int lane = tid & 31;
    int crow = tid >> 5;
#pragma unroll
    for (int kk = 0; kk < 8; kk++) {
        int c  = crow + (kk << 3);
        int tm = tm0 + lane;
        float val = 0.f;
        if (tm < 600) val = x[((size_t)(n * CC + c) * VV + v) * 600 + tm];
        sm[c][lane] = val;
    }
    __syncthreads();
    int c2 = tid & 63;
    int jb = tid >> 6;
#pragma unroll
    for (int kk = 0; kk < 8; kk++) {
        int j  = jb + (kk << 2);
        int tm = tm0 + j;
        if (tm < 600) {
            int t = tm >> 1, m = tm & 1;
            size_t row = ((size_t)((n * 2 + m) * VV + v)) * TT + t;
            g_xt[row * CC + c2] = sm[c2][j];
        }
    }
}

// ---------------------------------------------------------------------------
// Kernel B (tf32 mma): qkv = xt @ w_qkv + b_qkv   (60000 x 64 x 768)
// Block tile 64 rows x 128 cols, 256 threads. Warp = 16-row x 64-col slab.
// A frags cached in registers (full K=64); strides 68 -> conflict-free frags.
// Output section (q/k/v) chosen per block; k scaled by 1/16 at store.
// ---------------------------------------------------------------------------
__global__ __launch_bounds__(256) void kernB(const float* __restrict__ w,
                                             const float* __restrict__ b) {
    extern __shared__ float smB[];
    float* sxr = smB;              // 64 x 68  (A, row-major, tf32)
    float* swt = smB + 64 * 68;    // 128 x 68 (B^T: swt[n][k], tf32)
    int tid = threadIdx.x;
    int c0 = blockIdx.x * 128;
    int r0 = blockIdx.y * 64;

    for (int idx = tid; idx < 64 * 64; idx += 256) {
        int m = idx >> 6, e = idx & 63;
        int row = r0 + m;
        float v = (row < ROWS) ? g_xt[(size_t)row * CC + e] : 0.f;
        sxr[m * 68 + e] = tf32f(v);
    }
    for (int idx = tid; idx < 128 * 64; idx += 256) {
        int n = idx & 127, k = idx >> 7;
        swt[n * 68 + k] = tf32f(w[(size_t)k * 768 + c0 + n]);
    }
    __syncthreads();

    int wd = tid >> 5, lane = tid & 31;
    int gid = lane >> 2, tig = lane & 3;
    int mt = wd & 3, nh = wd >> 2;

    // A fragments: full K=64 (8 k-steps)
    unsigned af[8][4];
    {
        const float* q0 = sxr + (mt * 16 + gid) * 68;
        const float* q8 = q0 + 8 * 68;
#pragma unroll
        for (int ks = 0; ks < 8; ks++) {
            af[ks][0] = __float_as_uint(q0[ks * 8 + tig]);
            af[ks][1] = __float_as_uint(q8[ks * 8 + tig]);
            af[ks][2] = __float_as_uint(q0[ks * 8 + tig + 4]);
            af[ks][3] = __float_as_uint(q8[ks * 8 + tig + 4]);
        }
    }

    float* dst; float scale; int cb;
    if (c0 < 256)      { dst = g_q; scale = 1.0f;    cb = c0; }
    else if (c0 < 512) { dst = g_k; scale = 0.0625f; cb = c0 - 256; }
    else               { dst = g_v; scale = 1.0f;    cb = c0 - 512; }

#pragma unroll
    for (int nt2 = 0; nt2 < 8; nt2++) {
        int n0 = (nh * 8 + nt2) * 8;
        float a0 = 0.f, a1 = 0.f, a2 = 0.f, a3 = 0.f;
        const float* bs = swt + (n0 + gid) * 68;
#pragma unroll
        for (int ks = 0; ks < 8; ks++) {
            unsigned b0 = __float_as_uint(bs[ks * 8 + tig]);
            unsigned b1 = __float_as_uint(bs[ks * 8 + tig + 4]);
            MMA_TF32(a0, a1, a2, a3, af[ks][0], af[ks][1], af[ks][2], af[ks][3], b0, b1);
        }
        int col = cb + n0 + 2 * tig;
        float bb0 = b[c0 - cb + col];
        float bb1 = b[c0 - cb + col + 1];
        int r1 = r0 + mt * 16 + gid;
        if (r1 < ROWS)
            *(float2*)&dst[(size_t)r1 * EE + col] =
                make_float2((a0 + bb0) * scale, (a1 + bb1) * scale);
        int r2 = r1 + 8;
        if (r2 < ROWS)
            *(float2*)&dst[(size_t)r2 * EE + col] =
                make_float2((a2 + bb0) * scale, (a3 + bb1) * scale);
    }
}

// ---------------------------------------------------------------------------
// Kernel Attn (all-tensor tf32): block per (bv,h), 1024 threads, 32-row tiles.
//  phase R: scatter-store bias scores into sS at j = lr+299-r (bijection)
//  phase S: read-add-write Q.K^T into sS
//  softmax: warp-per-row, probs written back tf32-rounded in place
//  PV:      tensor mma P @ V with 4-way split-K over all 32 warps; groups
//           1..3 write C-frag partials to spv, group 0 finalizes.
//  sb holds 599 rows only; mma reads of rows 599..623 alias into sk and are
//  discarded (they always map to j<0). sv stride 32 with swizzle d'=(d+8j)&31.
// ---------------------------------------------------------------------------
__global__ __launch_bounds__(1024, 1) void kernAttn(const float* __restrict__ bias_table) {
    extern __shared__ float smem[];
    float* sb = smem;                    // 599 x 36 (tf32)
    float* sk = sb + 599 * 36;           // 304 x 36 (tf32) rows >=300 zero
    float* sv = sk + 304 * 36;           // 304 x 32 (tf32, swizzled)
    float* sq = sv + 304 * 32;           // 32 x 36 (tf32)
    float* sS = sq + 32 * 36;            // 32 x 308 scores -> probs
    float* spv = sS + 32 * 308;          // 3 x 1024 PV partials

    int head = blockIdx.x;
    int bv = head >> 3;
    int h  = head & 7;
    size_t row0 = (size_t)bv * TT;
    int tid = threadIdx.x;
    int w = tid >> 5, lane = tid & 31;
    int gid = lane >> 2, tig = lane & 3;

    // fills
    for (int idx = tid; idx < 599 * 32; idx += 1024) {
        int r = idx >> 5, d = idx & 31;
        sb[r * 36 + d] = tf32f(bias_table[r * 32 + d]);
    }
    for (int idx = tid; idx < 304 * 32; idx += 1024) {
        int j = idx >> 5, d = idx & 31;
        float kv = 0.f, vv = 0.f;
        if (j < 300) {
            size_t g = (row0 + j) * EE + h * HD + d;
            kv = g_k[g];
            vv = g_v[g];
        }
        sk[j * 36 + d] = tf32f(kv);
        sv[j * 32 + ((d + 8 * j) & 31)] = tf32f(vv);
    }

    int mt   = w & 1;        // m-tile for phase1 jobs
    int qidx = w >> 1;       // 0..15

    for (int l0 = 0; l0 < TT; l0 += 32) {
        __syncthreads();     // sS free (PV of prev tile done), sq free
        {
            int r = tid >> 5, d = lane;
            int l = l0 + r; if (l > 299) l = 299;
            sq[r * 36 + d] = tf32f(g_q[(row0 + l) * EE + h * HD + d]);
        }
        __syncthreads();

        // A fragments for this warp's m-tile
        unsigned af[4][4];
        {
            const float* q0 = sq + (mt * 16 + gid) * 36;
            const float* q8 = q0 + 8 * 36;
#pragma unroll
            for (int ks = 0; ks < 4; ks++) {
                af[ks][0] = __float_as_uint(q0[ks * 8 + tig]);
                af[ks][1] = __float_as_uint(q8[ks * 8 + tig]);
                af[ks][2] = __float_as_uint(q0[ks * 8 + tig + 4]);
                af[ks][3] = __float_as_uint(q8[ks * 8 + tig + 4]);
            }
        }

        // ---- phase R: scatter-store rel-position scores ----
        for (int nt = qidx; nt < 42; nt += 16) {
            float c0 = 0.f, c1 = 0.f, c2 = 0.f, c3 = 0.f;
            const float* bsrc = sb + (l0 + 8 * nt + gid) * 36;
#pragma unroll
            for (int ks = 0; ks < 4; ks++) {
                unsigned b0 = __float_as_uint(bsrc[ks * 8 + tig]);
                unsigned b1 = __float_as_uint(bsrc[ks * 8 + tig + 4]);
                MMA_TF32(c0, c1, c2, c3, af[ks][0], af[ks][1], af[ks][2], af[ks][3], b0, b1);
            }
            int lr = mt * 16 + gid;
            int jb = lr + 299 - 8 * nt - 2 * tig;
            if (jb >= 0 && jb < 304)         sS[lr * 308 + jb]           = c0;
            if (jb - 1 >= 0 && jb - 1 < 304) sS[lr * 308 + jb - 1]       = c1;
            int jb8 = jb + 8;
            if (jb8 >= 0 && jb8 < 304)         sS[(lr + 8) * 308 + jb8]     = c2;
            if (jb8 - 1 >= 0 && jb8 - 1 < 304) sS[(lr + 8) * 308 + jb8 - 1] = c3;
        }
        __syncthreads();

        // ---- phase S: add Q.K^T ----
        for (int nt = qidx; nt < 38; nt += 16) {
            float c0 = 0.f, c1 = 0.f, c2 = 0.f, c3 = 0.f;
            const float* bsrc = sk + (8 * nt + gid) * 36;
#pragma unroll
            for (int ks = 0; ks < 4; ks++) {
                unsigned b0 = __float_as_uint(bsrc[ks * 8 + tig]);
                unsigned b1 = __float_as_uint(bsrc[ks * 8 + tig + 4]);
                MMA_TF32(c0, c1, c2, c3, af[ks][0], af[ks][1], af[ks][2], af[ks][3], b0, b1);
            }
            float* p = sS + (mt * 16 + gid) * 308 + 8 * nt + 2 * tig;
            float2 e0 = *(float2*)p;
            e0.x += c0; e0.y += c1;
            *(float2*)p = e0;
            float* p2 = p + 8 * 308;
            float2 e1 = *(float2*)p2;
            e1.x += c2; e1.y += c3;
            *(float2*)p2 = e1;
        }
        __syncthreads();

        // ---- softmax: warp w handles row w ----
        {
            int l = l0 + w;
            float* row = sS + w * 308;
            if (l < TT) {
                float sc[10];
#pragma unroll
                for (int jj = 0; jj < 10; jj++) {
                    int j = lane + (jj << 5);
                    sc[jj] = (j < TT) ? row[j] : -3.0e38f;
                }
                float mx = sc[0];
#pragma unroll
                for (int jj = 1; jj < 10; jj++) mx = fmaxf(mx, sc[jj]);
#pragma unroll
                for (int off = 16; off > 0; off >>= 1)
                    mx = fmaxf(mx, __shfl_xor_sync(0xffffffffu, mx, off));
                float s = 0.f;
#pragma unroll
                for (int jj = 0; jj < 10; jj++) {
                    int j = lane + (jj << 5);
                    float e = (j < TT) ? __expf(sc[jj] - mx) : 0.f;
                    sc[jj] = e;
                    s += e;
                }
#pragma unroll
                for (int off = 16; off > 0; off >>= 1)
                    s += __shfl_xor_sync(0xffffffffu, s, off);
                float inv = 1.0f / s;
#pragma unroll
                for (int jj = 0; jj < 10; jj++) {
                    int j = lane + (jj << 5);
                    if (j < 304) row[j] = (j < TT) ? tf32f(sc[jj] * inv) : 0.f;
                }
            } else {
#pragma unroll
                for (int jj = 0; jj < 10; jj++) {
                    int j = lane + (jj << 5);
                    if (j < 304) row[j] = 0.f;
                }
            }
        }
        __syncthreads();

        // ---- PV: all 32 warps, 4-way split-K, P(16x304) @ V(304x8-tile) ----
        {
            int tile = w & 7;
            int pmt  = tile & 1;
            int n0   = (tile >> 1) * 8;
            int kh   = w >> 3;
            int ksA  = kh * 10;
            int ksB  = (kh == 3) ? 38 : ksA + 10;
            float c0 = 0.f, c1 = 0.f, c2 = 0.f, c3 = 0.f;
            const float* pa0 = sS + (pmt * 16 + gid) * 308;
            const float* pa8 = pa0 + 8 * 308;
#pragma unroll 2
            for (int ks = ksA; ks < ksB; ks++) {
                unsigned a0 = __float_as_uint(pa0[ks * 8 + tig]);
                unsigned a1 = __float_as_uint(pa8[ks * 8 + tig]);
                unsigned a2 = __float_as_uint(pa0[ks * 8 + tig + 4]);
                unsigned a3 = __float_as_uint(pa8[ks * 8 + tig + 4]);
                int k0r = ks * 8 + tig, k1r = k0r + 4;
                unsigned b0 = __float_as_uint(sv[k0r * 32 + ((n0 + gid + 8 * k0r) & 31)]);
                unsigned b1 = __float_as_uint(sv[k1r * 32 + ((n0 + gid + 8 * k1r) & 31)]);
                MMA_TF32(c0, c1, c2, c3, a0, a1, a2, a3, b0, b1);
            }
            if (kh) {
                *(float4*)(spv + (kh - 1) * 1024 + tile * 128 + lane * 4) =
                    make_float4(c0, c1, c2, c3);
            }
            __syncthreads();
            if (kh == 0) {
                float4 p0 = *(float4*)(spv + tile * 128 + lane * 4);
                float4 p1 = *(float4*)(spv + 1024 + tile * 128 + lane * 4);
                float4 p2 = *(float4*)(spv + 2048 + tile * 128 + lane * 4);
                c0 += p0.x + p1.x + p2.x;
                c1 += p0.y + p1.y + p2.y;
                c2 += p0.z + p1.z + p2.z;
                c3 += p0.w + p1.w + p2.w;
                int r1 = l0 + pmt * 16 + gid;
                int d0 = n0 + 2 * tig;
                if (r1 < TT)
                    *(float2*)&g_attn[(row0 + r1) * EE + h * HD + d0] = make_float2(c0, c1);
                int r2 = r1 + 8;
                if (r2 < TT)
                    *(float2*)&g_attn[(row0 + r2) * EE + h * HD + d0] = make_float2(c2, c3);
            }
        }
    }
}

// ---------------------------------------------------------------------------
// Kernel Merge: tiled GEMM out = attn @ w_merge + b_merge, scatter-store.
// ---------------------------------------------------------------------------
__global__ __launch_bounds__(256) void kernMerge(const float* __restrict__ wm,
                                                 const float* __restrict__ bm,
                                                 float* __restrict__ out) {
    __shared__ float sa[64 * 68];
    __shared__ float sw[64 * 68];
    int tid = threadIdx.x;
    int r0 = blockIdx.x * 64;
    int tx = tid & 15, ty = tid >> 4;

    float acc[4][4];
#pragma unroll
    for (int i = 0; i < 4; i++)
#pragma unroll
        for (int j = 0; j < 4; j++)
            acc[i][j] = bm[tx * 4 + j];

    for (int e0 = 0; e0 < 256; e0 += 64) {
        __syncthreads();
#pragma unroll
        for (int p = 0; p < 16; p++) {
            int idx = tid + p * 256;
            int a = idx >> 6;
            int e = idx & 63;
            int row = r0 + a;
            float va = 0.f;
            if (row < ROWS) va = g_attn[(size_t)row * EE + e0 + e];
            sa[e * 68 + a] = va;
            sw[a * 68 + e] = wm[(size_t)(e0 + a) * CC + e];
        }
        __syncthreads();
#pragma unroll
        for (int e = 0; e < 64; e++) {
            float4 a4 = *(const float4*)&sa[e * 68 + ty * 4];
            float4 b4 = *(const float4*)&sw[e * 68 + tx * 4];
            float av[4] = {a4.x, a4.y, a4.z, a4.w};
            float bv[4] = {b4.x, b4.y, b4.z, b4.w};
#pragma unroll
            for (int i = 0; i < 4; i++)
#pragma unroll
                for (int j = 0; j < 4; j++)
                    acc[i][j] = fmaf(av[i], bv[j], acc[i][j]);
        }
    }
#pragma unroll
    for (int i = 0; i < 4; i++) {
        int row = r0 + ty * 4 + i;
        if (row < ROWS) {
            int t  = row % 300;
            int vv = row / 300;
            int v  = vv % 25;
            int nm = vv / 25;
            int m  = nm & 1;
            int n  = nm >> 1;
#pragma unroll
            for (int j = 0; j < 4; j++) {
                int c = tx * 4 + j;
                out[(((size_t)(n * CC + c) * VV + v) * TT + t) * MM + m] = acc[i][j];
            }
        }
    }
}

// ---------------------------------------------------------------------------
extern "C" void kernel_launch(void* const* d_in, const int* in_sizes, int n_in,
                              void* d_out, int out_size) {
    const float* x          = (const float*)d_in[0];
    const float* w_qkv      = (const float*)d_in[1];
    const float* b_qkv      = (const float*)d_in[2];
    const float* w_merge    = (const float*)d_in[3];
    const float* b_merge    = (const float*)d_in[4];
    const float* bias_table = (const float*)d_in[5];
    float* out = (float*)d_out;

    int smem_attn = (599 * 36 + 304 * 36 + 304 * 32 + 32 * 36 + 32 * 308 + 3 * 1024) * 4;
    int smem_b    = (64 * 68 + 128 * 68) * 4;
    cudaFuncSetAttribute(kernAttn, cudaFuncAttributeMaxDynamicSharedMemorySize, smem_attn);
    cudaFuncSetAttribute(kernB,    cudaFuncAttributeMaxDynamicSharedMemorySize, smem_b);

    kernA<<<dim3(19, 25, 4), 256>>>(x);
    kernB<<<dim3(6, 938), 256, smem_b>>>(w_qkv, b_qkv);
    kernAttn<<<BVH, 1024, smem_attn>>>(bias_table);
    kernMerge<<<938, 256>>>(w_merge, b_merge, out);
}